// round 13
// baseline (speedup 1.0000x reference)
#include <cuda_runtime.h>
#include <cuda_bf16.h>
#include <cstdint>

#define BB 2
#define LL 4096
#define DIN 512
#define HH 8
#define DK 64
#define DV 64
#define DOUT 512

// ---------------------------------------------------------------------------
// Scratch (__device__ globals; no allocations allowed)
// ---------------------------------------------------------------------------
__device__ float g_Gp1[4 * BB * DIN * DIN];       // Gram partials XhXh (lower tiles) / step2 partials
__device__ float g_Gp2[4 * BB * DIN * DIN];       // Gram partials XhXl / step5 partials
__device__ float g_P [BB * HH * DK * DIN];        // P_all[b] (512x512)
__device__ float g_Mpart[8 * BB * HH * DK * DV];  // step-3 split-K partials
__device__ float g_M2[BB * HH * DK * DV];         // M[b,h] = P Wv
__device__ float g_T2[BB * DIN * (HH * DV)];      // T2cat[b] (512 x 512)

// bf16 hi/lo split arrays
__device__ __nv_bfloat16 g_xh [BB * LL * DIN];    // x direct  [b][l][d]
__device__ __nv_bfloat16 g_xl [BB * LL * DIN];
__device__ __nv_bfloat16 g_xTh[BB * DIN * LL];    // x^T       [b][d][l]
__device__ __nv_bfloat16 g_xTl[BB * DIN * LL];
__device__ __nv_bfloat16 g_FTh[BB * DOUT * DIN];  // F^T       [b][o][d]
__device__ __nv_bfloat16 g_FTl[BB * DOUT * DIN];
__device__ __nv_bfloat16 g_Gh [BB * DIN * DIN];   // G bf16 hi (symmetric)
__device__ __nv_bfloat16 g_Gl [BB * DIN * DIN];   // G bf16 lo
__device__ __nv_bfloat16 g_WkTh[HH * DK * DIN];   // WkT flat: row h*64+k, col d
__device__ __nv_bfloat16 g_WkTl[HH * DK * DIN];

// lower-triangle tile LUT for the Gram product-1 (4x4 tile grid, by >= bx)
__device__ __constant__ int c_tri_i[10] = {0,1,1,2,2,2,3,3,3,3};
__device__ __constant__ int c_tri_j[10] = {0,0,1,0,1,2,0,1,2,3};

// ---------------------------------------------------------------------------
// Helpers
// ---------------------------------------------------------------------------
__device__ __forceinline__ uint32_t smem_u32(const void* p) {
    uint32_t a;
    asm("{ .reg .u64 t; cvta.to.shared.u64 t, %1; cvt.u32.u64 %0, t; }" : "=r"(a) : "l"(p));
    return a;
}
__device__ __forceinline__ void cp_async16(uint32_t saddr, const void* gptr) {
    asm volatile("cp.async.ca.shared.global [%0], [%1], 16;" :: "r"(saddr), "l"(gptr));
}
__device__ __forceinline__ void ldm4(uint32_t* r, uint32_t addr) {
    asm volatile("ldmatrix.sync.aligned.m8n8.x4.shared.b16 {%0,%1,%2,%3}, [%4];"
        : "=r"(r[0]), "=r"(r[1]), "=r"(r[2]), "=r"(r[3]) : "r"(addr));
}
__device__ __forceinline__ void mma16816(float* c, const uint32_t* a,
                                         uint32_t b0, uint32_t b1) {
    asm volatile(
        "mma.sync.aligned.m16n8k16.row.col.f32.bf16.bf16.f32 "
        "{%0,%1,%2,%3}, {%4,%5,%6,%7}, {%8,%9}, {%0,%1,%2,%3};"
        : "+f"(c[0]), "+f"(c[1]), "+f"(c[2]), "+f"(c[3])
        : "r"(a[0]), "r"(a[1]), "r"(a[2]), "r"(a[3]), "r"(b0), "r"(b1));
}
__device__ __forceinline__ void bf16split(float v, __nv_bfloat16& h, __nv_bfloat16& l) {
    h = __float2bfloat16(v);
    l = __float2bfloat16(v - __bfloat162float(h));
}

// ---------------------------------------------------------------------------
// Split / prep kernels
// ---------------------------------------------------------------------------
__global__ __launch_bounds__(256) void split_x_kernel(
    const float* __restrict__ x,
    __nv_bfloat16* __restrict__ xh, __nv_bfloat16* __restrict__ xl,
    __nv_bfloat16* __restrict__ xTh, __nv_bfloat16* __restrict__ xTl)
{
    __shared__ float tile[32][33];
    const int tx = threadIdx.x, ty = threadIdx.y;
    const int b = blockIdx.z, d0 = blockIdx.x * 32, l0 = blockIdx.y * 32;
    const float* xb = x + (long)b * LL * DIN;

#pragma unroll
    for (int i = ty; i < 32; i += 8) {
        float v = xb[(long)(l0 + i) * DIN + d0 + tx];
        tile[i][tx] = v;
        __nv_bfloat16 h, lo; bf16split(v, h, lo);
        long o = (long)b * LL * DIN + (long)(l0 + i) * DIN + d0 + tx;
        xh[o] = h; xl[o] = lo;
    }
    __syncthreads();
#pragma unroll
    for (int i = ty; i < 32; i += 8) {
        float v = tile[tx][i];
        __nv_bfloat16 h, lo; bf16split(v, h, lo);
        long o = (long)b * DIN * LL + (long)(d0 + i) * LL + l0 + tx;
        xTh[o] = h; xTl[o] = lo;
    }
}

// WkT[h*64+k][d] = Wk[h][d][k], bf16 hi/lo
__global__ __launch_bounds__(256) void prep_WkT_kernel(
    const float* __restrict__ Wk,
    __nv_bfloat16* __restrict__ WkTh, __nv_bfloat16* __restrict__ WkTl)
{
    __shared__ float tile[32][33];
    const int tx = threadIdx.x, ty = threadIdx.y;
    const int h = blockIdx.z, k0 = blockIdx.x * 32, d0 = blockIdx.y * 32;
    const float* W = Wk + (long)h * DIN * DK;

#pragma unroll
    for (int r = ty; r < 32; r += 8)
        tile[r][tx] = W[(long)(d0 + r) * DK + k0 + tx];
    __syncthreads();
#pragma unroll
    for (int ii = ty; ii < 32; ii += 8) {
        float v = tile[tx][ii];
        __nv_bfloat16 hh, lo; bf16split(v, hh, lo);
        long o = (long)(h * DK + k0 + ii) * DIN + d0 + tx;
        WkTh[o] = hh; WkTl[o] = lo;
    }
}

// Symmetric reduceG v2: one CTA per unordered 32x32 tile pair (I >= J).
// Gt = sum_p Gp1[I,J] + sum_p Gp2[I,J] + (sum_p Gp2[J,I])^T
// Writes G[I,J] = Gt and G[J,I] = Gt^T (bf16 hi/lo).  Gp1 valid lower only.
__global__ __launch_bounds__(256) void reduceG2_kernel(
    const float* __restrict__ Gp1, const float* __restrict__ Gp2,
    __nv_bfloat16* __restrict__ Gh, __nv_bfloat16* __restrict__ Gl)
{
    __shared__ float B2s[32][33];
    __shared__ float Gt[32][33];
    const int tx = threadIdx.x, ty = threadIdx.y;
    const int b = blockIdx.z;
    int p = blockIdx.x;
    int I = (int)((sqrtf(8.f * p + 1.f) - 1.f) * 0.5f);
    while ((I + 1) * (I + 2) / 2 <= p) I++;
    while (I * (I + 1) / 2 > p) I--;
    const int J = p - I * (I + 1) / 2;
    const int i0 = I * 32, j0 = J * 32;

    const long GSL = (long)DIN * DIN;
    const long PS = (long)BB * GSL;
    const float* G1 = Gp1 + b * GSL;
    const float* G2 = Gp2 + b * GSL;

    // B2s[r][c] = sum_p Gp2[j0+r][i0+c]
#pragma unroll
    for (int r = ty; r < 32; r += 8) {
        float s = 0.f;
#pragma unroll
        for (int q = 0; q < 4; q++)
            s += G2[q * PS + (long)(j0 + r) * DIN + i0 + tx];
        B2s[r][tx] = s;
    }
    __syncthreads();

#pragma unroll
    for (int r = ty; r < 32; r += 8) {
        float s = 0.f;
#pragma unroll
        for (int q = 0; q < 4; q++) {
            const long ro = q * PS + (long)(i0 + r) * DIN + j0 + tx;
            s += G1[ro] + G2[ro];
        }
        float v = s + B2s[tx][r];
        Gt[r][tx] = v;
        __nv_bfloat16 h, lo; bf16split(v, h, lo);
        const long o = b * GSL + (long)(i0 + r) * DIN + j0 + tx;
        Gh[o] = h; Gl[o] = lo;
    }

    if (I != J) {
        __syncthreads();
#pragma unroll
        for (int r = ty; r < 32; r += 8) {
            float v = Gt[tx][r];
            __nv_bfloat16 h, lo; bf16split(v, h, lo);
            const long o = b * GSL + (long)(j0 + r) * DIN + i0 + tx;
            Gh[o] = h; Gl[o] = lo;
        }
    }
}

// FT[b][o][d] = split( sum_p Fp[p][b][d][o] )  — fused reduce + transpose + split
__global__ __launch_bounds__(256) void reduceF_splitFT_kernel(
    const float* __restrict__ Fp,
    __nv_bfloat16* __restrict__ FTh, __nv_bfloat16* __restrict__ FTl)
{
    __shared__ float tile[32][33];
    const int tx = threadIdx.x, ty = threadIdx.y;
    const int b = blockIdx.z, o0 = blockIdx.x * 32, d0 = blockIdx.y * 32;
    const long FS = (long)DIN * DOUT;
    const long PS = (long)BB * FS;

#pragma unroll
    for (int i = ty; i < 32; i += 8) {
        float s = 0.f;
#pragma unroll
        for (int p = 0; p < 4; p++)
            s += Fp[p * PS + b * FS + (long)(d0 + i) * DOUT + o0 + tx];
        tile[i][tx] = s;
    }
    __syncthreads();
#pragma unroll
    for (int i = ty; i < 32; i += 8) {
        float v = tile[tx][i];
        __nv_bfloat16 h, lo; bf16split(v, h, lo);
        long o = (long)b * DOUT * DIN + (long)(o0 + i) * DIN + d0 + tx;
        FTh[o] = h; FTl[o] = lo;
    }
}

// ---------------------------------------------------------------------------
// bf16 tensor GEMM: C[128x128 fp32] = sum_k A[m,k]*B[n,k]
// PR=3: AhBh + AhBl + AlBh.  PR=1: AhBh only.
// GRAM=1: 1-D grid decode — per batch: 10*nsplit product-1 CTAs (lower tiles,
//         C=Gp1) then 16*nsplit product-2 CTAs (all tiles, B=Bl, C2=Gp2).
// ---------------------------------------------------------------------------
template <int PR, int KTv, int GRAM>
__global__ __launch_bounds__(256, 2) void tgemm_bf16(
    const __nv_bfloat16* __restrict__ Ah, const __nv_bfloat16* __restrict__ Al,
    const __nv_bfloat16* __restrict__ Bh, const __nv_bfloat16* __restrict__ Bl,
    float* __restrict__ C, float* __restrict__ C2,
    int K, int lda, int ldb, int ldc,
    long sAb, long sBb, long sCb, int nsplit, long splitStride)
{
    constexpr int STRIDEv = KTv + 8;
    constexpr int TILE = 128 * STRIDEv * 2;
    constexpr int NTILE = (PR == 1) ? 2 : 4;
    constexpr int BUF_Bv = NTILE * TILE;
    constexpr int S_AH = 0;
    constexpr int S_AL = (PR == 1) ? 0 : TILE;
    constexpr int S_BH = (PR == 1) ? TILE : 2 * TILE;
    constexpr int S_BL = (PR == 1) ? TILE : 3 * TILE;
    constexpr int SEGS = KTv / 8;

    extern __shared__ char sm[];
    const uint32_t sb = smem_u32(sm);

    const int tid = threadIdx.x;
    const int w = tid >> 5;
    const int lane = tid & 31;
    const int gid = lane >> 2;
    const int q = lane & 3;
    const int wr = w & 3;
    const int wc = w >> 2;

    int b, split, by, bx;
    if (GRAM) {
        // grid = (BB * (10 + 16) * nsplit, 1, 1)
        const int per_b = 26 * nsplit;
        int zz = blockIdx.x;
        b = zz / per_b;
        int r = zz % per_b;
        if (r < 10 * nsplit) {
            split = r / 10;
            const int t = r % 10;
            by = c_tri_i[t]; bx = c_tri_j[t];
        } else {
            r -= 10 * nsplit;
            split = r / 16;
            const int t = r % 16;
            by = t >> 2; bx = t & 3;
            Bh = Bl; C = C2;
        }
    } else {
        int z = blockIdx.z;
        split = z % nsplit;
        b = z / nsplit;
        by = blockIdx.y; bx = blockIdx.x;
    }
    Ah += (long)b * sAb; Al += (long)b * sAb;
    Bh += (long)b * sBb; Bl += (long)b * sBb;
    C += (long)b * sCb + (long)split * splitStride;

    const int m0 = by * 128;
    const int n0 = bx * 128;
    const int Kc = K / nsplit;
    const int k0 = split * Kc;
    const int nchunks = Kc / KTv;

    float c[2][8][4];
#pragma unroll
    for (int mt = 0; mt < 2; mt++)
#pragma unroll
        for (int nt = 0; nt < 8; nt++)
#pragma unroll
            for (int i = 0; i < 4; i++) c[mt][nt][i] = 0.f;

    auto issue = [&](int ch, int buf) {
        const int kc = k0 + ch * KTv;
        const uint32_t base = sb + buf * BUF_Bv;
#pragma unroll
        for (int t = 0; t < 4; t++) {
            if (PR == 1 && (t & 1)) continue;
            const __nv_bfloat16* gp = (t == 0) ? Ah : (t == 1) ? Al : (t == 2) ? Bh : Bl;
            const int off = (t == 0) ? S_AH : (t == 1) ? S_AL : (t == 2) ? S_BH : S_BL;
            const int ld = (t < 2) ? lda : ldb;
            const int rb = (t < 2) ? m0 : n0;
#pragma unroll
            for (int p = 0; p < KTv / 16; p++) {
                const int f = p * 256 + tid;
                const int row = f / SEGS;
                const int seg = f % SEGS;
                cp_async16(base + off + (row * STRIDEv + seg * 8) * 2,
                           gp + (long)(rb + row) * ld + kc + seg * 8);
            }
        }
        asm volatile("cp.async.commit_group;" ::: "memory");
    };

    issue(0, 0);

    const int lrow = (lane & 7) + ((lane >> 3) & 1) * 8;
    const int lcol = (lane >> 4) * 8;

    for (int ch = 0; ch < nchunks; ch++) {
        const int cur = ch & 1;
        if (ch + 1 < nchunks) {
            issue(ch + 1, cur ^ 1);
            asm volatile("cp.async.wait_group 1;" ::: "memory");
        } else {
            asm volatile("cp.async.wait_group 0;" ::: "memory");
        }
        __syncthreads();

        const uint32_t base = sb + cur * BUF_Bv;
#pragma unroll
        for (int ks = 0; ks < KTv / 16; ks++) {
            const int kb = ks * 16;
#pragma unroll
            for (int pr = 0; pr < PR; pr++) {
                const uint32_t pa = base + ((pr == 2) ? S_AL : S_AH);
                const uint32_t pb = base + ((pr == 1) ? S_BL : S_BH);

                uint32_t a[2][4];
#pragma unroll
                for (int mt = 0; mt < 2; mt++) {
                    const int row = wr * 32 + mt * 16 + lrow;
                    ldm4(a[mt], pa + (row * STRIDEv + kb + lcol) * 2);
                }
#pragma unroll
                for (int ng = 0; ng < 4; ng++) {
                    const int row = wc * 64 + ng * 16 + lrow;
                    uint32_t bm[4];
                    ldm4(bm, pb + (row * STRIDEv + kb + lcol) * 2);
                    mma16816(c[0][ng * 2],     a[0], bm[0], bm[2]);
                    mma16816(c[0][ng * 2 + 1], a[0], bm[1], bm[3]);
                    mma16816(c[1][ng * 2],     a[1], bm[0], bm[2]);
                    mma16816(c[1][ng * 2 + 1], a[1], bm[1], bm[3]);
                }
            }
        }
        __syncthreads();
    }

#pragma unroll
    for (int mt = 0; mt < 2; mt++) {
        const int r = m0 + wr * 32 + mt * 16 + gid;
#pragma unroll
        for (int nt = 0; nt < 8; nt++) {
            const int col = n0 + wc * 64 + nt * 8 + q * 2;
            *(float2*)(C + (long)r * ldc + col)       = make_float2(c[mt][nt][0], c[mt][nt][1]);
            *(float2*)(C + (long)(r + 8) * ldc + col) = make_float2(c[mt][nt][2], c[mt][nt][3]);
        }
    }
}

// ---------------------------------------------------------------------------
// Small fp32 GEMM: 64x64 tile (middle chain steps 3-5)
// ---------------------------------------------------------------------------
template <int TRANSA>
__global__ __launch_bounds__(256) void gemm64(
    const float* __restrict__ A, const float* __restrict__ B, float* __restrict__ C,
    int M, int N, int K,
    int lda, int ldb, int ldc,
    long sAb, long sAh, long sBb, long sBh, long sCb, long sCh,
    int nh, int nsplit, long splitStride)
{
    int z = blockIdx.z;
    int split = z % nsplit; z /= nsplit;
    int h = z % nh;
    int b = z / nh;
    A += (long)b * sAb + (long)h * sAh;
    B += (long)b * sBb + (long)h * sBh;
    C += (long)b * sCb + (long)h * sCh + (long)split * splitStride;

    const int Kc = K / nsplit;
    const int k0 = split * Kc;

    __shared__ float As[16][64];
    __shared__ float Bs[16][64];

    const int m0 = blockIdx.y * 64;
    const int n0 = blockIdx.x * 64;
    const int tid = threadIdx.x;
    const int tx = tid & 15;
    const int ty = tid >> 4;

    float acc[4][4];
#pragma unroll
    for (int i = 0; i < 4; i++)
#pragma unroll
        for (int j = 0; j < 4; j++) acc[i][j] = 0.f;

    for (int kt = 0; kt < Kc; kt += 16) {
        if (TRANSA) {
            int k  = tid >> 4;
            int m4 = (tid & 15) * 4;
            float4 v = *reinterpret_cast<const float4*>(
                &A[(long)(k0 + kt + k) * lda + m0 + m4]);
            *reinterpret_cast<float4*>(&As[k][m4]) = v;
        } else {
            int m  = tid >> 2;
            int k4 = (tid & 3) * 4;
            float4 v = *reinterpret_cast<const float4*>(
                &A[(long)(m0 + m) * lda + (k0 + kt + k4)]);
            As[k4 + 0][m] = v.x;
            As[k4 + 1][m] = v.y;
            As[k4 + 2][m] = v.z;
            As[k4 + 3][m] = v.w;
        }
        {
            int k  = tid >> 4;
            int n4 = (tid & 15) * 4;
            float4 v = *reinterpret_cast<const float4*>(
                &B[(long)(k0 + kt + k) * ldb + n0 + n4]);
            *reinterpret_cast<float4*>(&Bs[k][n4]) = v;
        }
        __syncthreads();

#pragma unroll
        for (int k = 0; k < 16; k++) {
            float4 a = *reinterpret_cast<const float4*>(&As[k][ty * 4]);
            float4 bb = *reinterpret_cast<const float4*>(&Bs[k][tx * 4]);
            float av[4] = {a.x, a.y, a.z, a.w};
            float bv[4] = {bb.x, bb.y, bb.z, bb.w};
#pragma unroll
            for (int i = 0; i < 4; i++)
#pragma unroll
                for (int j = 0; j < 4; j++)
                    acc[i][j] += av[i] * bv[j];
        }
        __syncthreads();
    }

#pragma unroll
    for (int i = 0; i < 4; i++) {
        int m = m0 + ty * 4 + i;
        float4 v = make_float4(acc[i][0], acc[i][1], acc[i][2], acc[i][3]);
        *reinterpret_cast<float4*>(&C[(long)m * ldc + n0 + tx * 4]) = v;
    }
}

// Deterministic fixed-order reduction of split-K partials (scalar)
template <int P>
__global__ void reduceP(float* __restrict__ dst, const float* __restrict__ src, int n)
{
    int i = blockIdx.x * 256 + threadIdx.x;
    if (i < n) {
        float s = 0.f;
#pragma unroll
        for (int p = 0; p < P; p++) s += src[(long)p * n + i];
        dst[i] = s;
    }
}

// float4-vectorized variant (n % 4 == 0)
template <int P>
__global__ void reduceP4(float* __restrict__ dst, const float* __restrict__ src, int n4)
{
    int i = blockIdx.x * 256 + threadIdx.x;
    if (i < n4) {
        const float4* s4 = (const float4*)src;
        float4 acc = s4[i];
#pragma unroll
        for (int p = 1; p < P; p++) {
            float4 v = s4[(long)p * n4 + i];
            acc.x += v.x; acc.y += v.y; acc.z += v.z; acc.w += v.w;
        }
        ((float4*)dst)[i] = acc;
    }
}

// ---------------------------------------------------------------------------
extern "C" void kernel_launch(void* const* d_in, const int* in_sizes, int n_in,
                              void* d_out, int out_size)
{
    const float* x  = (const float*)d_in[0];
    const float* Wq = (const float*)d_in[1];
    const float* Wk = (const float*)d_in[2];
    const float* Wv = (const float*)d_in[3];
    const float* Wo = (const float*)d_in[4];
    float* out = (float*)d_out;

    float *Gp1, *Gp2, *P, *Mp, *M2, *T2;
    cudaGetSymbolAddress((void**)&Gp1, g_Gp1);
    cudaGetSymbolAddress((void**)&Gp2, g_Gp2);
    cudaGetSymbolAddress((void**)&P,   g_P);
    cudaGetSymbolAddress((void**)&Mp,  g_Mpart);
    cudaGetSymbolAddress((void**)&M2,  g_M2);
    cudaGetSymbolAddress((void**)&T2,  g_T2);

    __nv_bfloat16 *xh, *xl, *xTh, *xTl, *FTh, *FTl, *Gh, *Gl, *WkTh, *WkTl;
    cudaGetSymbolAddress((void**)&xh,   g_xh);
    cudaGetSymbolAddress((void**)&xl,   g_xl);
    cudaGetSymbolAddress((void**)&xTh,  g_xTh);
    cudaGetSymbolAddress((void**)&xTl,  g_xTl);
    cudaGetSymbolAddress((void**)&FTh,  g_FTh);
    cudaGetSymbolAddress((void**)&FTl,  g_FTl);
    cudaGetSymbolAddress((void**)&Gh,   g_Gh);
    cudaGetSymbolAddress((void**)&Gl,   g_Gl);
    cudaGetSymbolAddress((void**)&WkTh, g_WkTh);
    cudaGetSymbolAddress((void**)&WkTl, g_WkTl);

    const int TG1_SMEM = 2 * 2 * (128 * 72 * 2);   // KT=64, PR=1: 73728
    const int TG3_SMEM = 2 * 4 * (128 * 40 * 2);   // KT=32, PR=3: 81920
    cudaFuncSetAttribute((const void*)tgemm_bf16<1, 64, 1>,
                         cudaFuncAttributeMaxDynamicSharedMemorySize, TG1_SMEM);
    cudaFuncSetAttribute((const void*)tgemm_bf16<3, 32, 0>,
                         cudaFuncAttributeMaxDynamicSharedMemorySize, TG3_SMEM);

    const long LD   = (long)LL * DIN;
    const long GS   = (long)DIN * DIN;
    const long WKS  = (long)DIN * DK;
    const long PSH  = (long)DK * DIN;
    const long PSB  = (long)HH * PSH;
    const long MSH  = (long)DK * DV;
    const long MSB  = (long)HH * MSH;
    const long XTS  = (long)DIN * LL;

    // 0) split x; prep WkT
    split_x_kernel<<<dim3(DIN / 32, LL / 32, BB), dim3(32, 8)>>>(x, xh, xl, xTh, xTl);
    prep_WkT_kernel<<<dim3(DK / 32, DIN / 32, HH), dim3(32, 8)>>>(Wk, WkTh, WkTl);

    // 1) Gram, symmetric: product 1 lower-triangle tiles only (10), product 2 all 16.
    //    1-D grid: BB * (10 + 16) * 4 = 208 CTAs, split-K=4.
    tgemm_bf16<1, 64, 1><<<BB * 26 * 4, 256, TG1_SMEM>>>(
        xTh, xTh, xTh, xTl, Gp1, Gp2,
        LL, LL, LL, DIN, XTS, XTS, GS, 4, (long)BB * GS);
    // symmetric reduce: 136 tile-pairs per batch
    reduceG2_kernel<<<dim3(136, 1, BB), dim3(32, 8)>>>(Gp1, Gp2, Gh, Gl);

    // 2) P_all[b] = WkT_flat @ G[b]  (split-K=4 -> grid 128; partials reuse Gp1)
    tgemm_bf16<3, 32, 0><<<dim3(4, 4, BB * 4), 256, TG3_SMEM>>>(
        WkTh, WkTl, Gh, Gl, Gp1, Gp1,
        DIN, DIN, DIN, DIN, 0, GS, GS, 4, (long)BB * GS);
    reduceP4<4><<<(int)((BB * GS / 4 + 255) / 256), 256>>>(P, Gp1, (int)(BB * GS / 4));

    // 3) M[b,h] = P[b,h] @ Wv[h]  (64x64, K=512), split-K=8 -> 128 CTAs
    gemm64<0><<<dim3(1, 1, BB * HH * 8), 256>>>(
        P, Wv, Mp, DK, DV, DIN,
        DIN, DV, DV,
        PSB, PSH, 0, WKS, MSB, MSH,
        HH, 8, (long)BB * HH * DK * DV);
    reduceP4<8><<<(BB * HH * DK * DV / 4 + 255) / 256, 256>>>(M2, Mp, BB * HH * DK * DV / 4);

    // 4) T2cat[b][:, h*64:] = Wq[h] @ M[b,h]  (512x64, K=64), 128 CTAs
    gemm64<0><<<dim3(1, 8, BB * HH), 256>>>(
        Wq, M2, T2, DIN, DV, DK,
        DK, DV, HH * DV,
        0, WKS, MSB, MSH, (long)DIN * HH * DV, (long)DV,
        HH, 1, 0);

    // 5) F partials = T2cat[b] @ Wo_flat  (split-K=4 -> 256 CTAs; partials in Gp2)
    gemm64<0><<<dim3(8, 8, BB * 4), 256>>>(
        T2, Wo, Gp2, DIN, DOUT, HH * DV,
        HH * DV, DOUT, DOUT,
        (long)DIN * HH * DV, 0, 0, 0, (long)DIN * DOUT, 0,
        1, 4, (long)BB * DIN * DOUT);

    // 5b) fused: F = sum partials; FT bf16 hi/lo (transposed) in one pass
    reduceF_splitFT_kernel<<<dim3(DOUT / 32, DIN / 32, BB), dim3(32, 8)>>>(Gp2, FTh, FTl);

    // 6) out[b] = x[b] @ F[b]  (tensor, 3-product), 256 CTAs
    tgemm_bf16<3, 32, 0><<<dim3(4, 32, BB), 256, TG3_SMEM>>>(
        xh, xl, FTh, FTl, out, out,
        DIN, DIN, DIN, DOUT,
        LD, (long)DOUT * DIN, (long)LL * DOUT, 1, 0);
}

// round 14
// speedup vs baseline: 1.0537x; 1.0537x over previous
#include <cuda_runtime.h>
#include <cuda_bf16.h>
#include <cstdint>

#define BB 2
#define LL 4096
#define DIN 512
#define HH 8
#define DK 64
#define DV 64
#define DOUT 512

// ---------------------------------------------------------------------------
// Scratch (__device__ globals; no allocations allowed)
// ---------------------------------------------------------------------------
__device__ float g_Gp1[4 * BB * DIN * DIN];       // Gram partials XhXh / step2 partials
__device__ float g_Gp2[4 * BB * DIN * DIN];       // Gram partials XhXl / step5 partials
__device__ float g_P [BB * HH * DK * DIN];        // P_all[b] (512x512)
__device__ float g_Mpart[8 * BB * HH * DK * DV];  // step-3 split-K partials
__device__ float g_M2[BB * HH * DK * DV];         // M[b,h] = P Wv
__device__ float g_T2[BB * DIN * (HH * DV)];      // T2cat[b] (512 x 512)

// bf16 hi/lo split arrays
__device__ __nv_bfloat16 g_xh [BB * LL * DIN];    // x direct  [b][l][d]
__device__ __nv_bfloat16 g_xl [BB * LL * DIN];
__device__ __nv_bfloat16 g_xTh[BB * DIN * LL];    // x^T       [b][d][l]
__device__ __nv_bfloat16 g_xTl[BB * DIN * LL];
__device__ __nv_bfloat16 g_FTh[BB * DOUT * DIN];  // F^T       [b][o][d]
__device__ __nv_bfloat16 g_FTl[BB * DOUT * DIN];
__device__ __nv_bfloat16 g_Gh [BB * DIN * DIN];   // G bf16 hi (symmetric)
__device__ __nv_bfloat16 g_Gl [BB * DIN * DIN];   // G bf16 lo
__device__ __nv_bfloat16 g_WkTh[HH * DK * DIN];   // WkT flat: row h*64+k, col d
__device__ __nv_bfloat16 g_WkTl[HH * DK * DIN];

// ---------------------------------------------------------------------------
// Helpers
// ---------------------------------------------------------------------------
__device__ __forceinline__ uint32_t smem_u32(const void* p) {
    uint32_t a;
    asm("{ .reg .u64 t; cvta.to.shared.u64 t, %1; cvt.u32.u64 %0, t; }" : "=r"(a) : "l"(p));
    return a;
}
__device__ __forceinline__ void cp_async16(uint32_t saddr, const void* gptr) {
    asm volatile("cp.async.ca.shared.global [%0], [%1], 16;" :: "r"(saddr), "l"(gptr));
}
__device__ __forceinline__ void ldm4(uint32_t* r, uint32_t addr) {
    asm volatile("ldmatrix.sync.aligned.m8n8.x4.shared.b16 {%0,%1,%2,%3}, [%4];"
        : "=r"(r[0]), "=r"(r[1]), "=r"(r[2]), "=r"(r[3]) : "r"(addr));
}
__device__ __forceinline__ void mma16816(float* c, const uint32_t* a,
                                         uint32_t b0, uint32_t b1) {
    asm volatile(
        "mma.sync.aligned.m16n8k16.row.col.f32.bf16.bf16.f32 "
        "{%0,%1,%2,%3}, {%4,%5,%6,%7}, {%8,%9}, {%0,%1,%2,%3};"
        : "+f"(c[0]), "+f"(c[1]), "+f"(c[2]), "+f"(c[3])
        : "r"(a[0]), "r"(a[1]), "r"(a[2]), "r"(a[3]), "r"(b0), "r"(b1));
}
__device__ __forceinline__ void bf16split(float v, __nv_bfloat16& h, __nv_bfloat16& l) {
    h = __float2bfloat16(v);
    l = __float2bfloat16(v - __bfloat162float(h));
}
// split 4 floats -> packed hi (uint2) + lo (uint2)
__device__ __forceinline__ void split4pack(const float* v, uint2& hp, uint2& lp) {
    __nv_bfloat16 h[4], l[4];
#pragma unroll
    for (int i = 0; i < 4; i++) bf16split(v[i], h[i], l[i]);
    hp.x = (uint32_t)__bfloat16_as_ushort(h[0]) | ((uint32_t)__bfloat16_as_ushort(h[1]) << 16);
    hp.y = (uint32_t)__bfloat16_as_ushort(h[2]) | ((uint32_t)__bfloat16_as_ushort(h[3]) << 16);
    lp.x = (uint32_t)__bfloat16_as_ushort(l[0]) | ((uint32_t)__bfloat16_as_ushort(l[1]) << 16);
    lp.y = (uint32_t)__bfloat16_as_ushort(l[2]) | ((uint32_t)__bfloat16_as_ushort(l[3]) << 16);
}

// ---------------------------------------------------------------------------
// Split / prep kernels
// ---------------------------------------------------------------------------
__global__ __launch_bounds__(256) void split_x_kernel(
    const float* __restrict__ x,
    __nv_bfloat16* __restrict__ xh, __nv_bfloat16* __restrict__ xl,
    __nv_bfloat16* __restrict__ xTh, __nv_bfloat16* __restrict__ xTl)
{
    __shared__ float tile[32][33];
    const int tx = threadIdx.x, ty = threadIdx.y;
    const int b = blockIdx.z, d0 = blockIdx.x * 32, l0 = blockIdx.y * 32;
    const float* xb = x + (long)b * LL * DIN;

#pragma unroll
    for (int i = ty; i < 32; i += 8) {
        float v = xb[(long)(l0 + i) * DIN + d0 + tx];
        tile[i][tx] = v;
        __nv_bfloat16 h, lo; bf16split(v, h, lo);
        long o = (long)b * LL * DIN + (long)(l0 + i) * DIN + d0 + tx;
        xh[o] = h; xl[o] = lo;
    }
    __syncthreads();
#pragma unroll
    for (int i = ty; i < 32; i += 8) {
        float v = tile[tx][i];
        __nv_bfloat16 h, lo; bf16split(v, h, lo);
        long o = (long)b * DIN * LL + (long)(d0 + i) * LL + l0 + tx;
        xTh[o] = h; xTl[o] = lo;
    }
}

// WkT[h*64+k][d] = Wk[h][d][k], bf16 hi/lo
__global__ __launch_bounds__(256) void prep_WkT_kernel(
    const float* __restrict__ Wk,
    __nv_bfloat16* __restrict__ WkTh, __nv_bfloat16* __restrict__ WkTl)
{
    __shared__ float tile[32][33];
    const int tx = threadIdx.x, ty = threadIdx.y;
    const int h = blockIdx.z, k0 = blockIdx.x * 32, d0 = blockIdx.y * 32;
    const float* W = Wk + (long)h * DIN * DK;

#pragma unroll
    for (int r = ty; r < 32; r += 8)
        tile[r][tx] = W[(long)(d0 + r) * DK + k0 + tx];
    __syncthreads();
#pragma unroll
    for (int ii = ty; ii < 32; ii += 8) {
        float v = tile[tx][ii];
        __nv_bfloat16 hh, lo; bf16split(v, hh, lo);
        long o = (long)(h * DK + k0 + ii) * DIN + d0 + tx;
        WkTh[o] = hh; WkTl[o] = lo;
    }
}

// Vectorized reduceG: G = sum_p Gp1 + sum_p Gp2 + (sum_p Gp2)^T ; bf16 hi/lo.
// grid (16,16,BB), 256 threads; float4 global loads, uint2 packed stores.
__global__ __launch_bounds__(256) void reduceG_kernel(
    const float* __restrict__ Gp1, const float* __restrict__ Gp2,
    __nv_bfloat16* __restrict__ Gh, __nv_bfloat16* __restrict__ Gl)
{
    __shared__ float T[32][33];
    const int tid = threadIdx.x;
    const int row = tid >> 3;          // 0..31
    const int c4 = (tid & 7) * 4;      // 0,4,...,28
    const int b = blockIdx.z, j0 = blockIdx.x * 32, i0 = blockIdx.y * 32;
    const long GSL = (long)DIN * DIN;
    const long PS = (long)BB * GSL;

    // phase 1: T[r][c] = sum_p Gp2[b][j0+r][i0+c]   (float4 loads)
    {
        float4 s = make_float4(0.f, 0.f, 0.f, 0.f);
#pragma unroll
        for (int p = 0; p < 4; p++) {
            float4 v = *(const float4*)&Gp2[p * PS + b * GSL + (long)(j0 + row) * DIN + i0 + c4];
            s.x += v.x; s.y += v.y; s.z += v.z; s.w += v.w;
        }
        T[row][c4 + 0] = s.x; T[row][c4 + 1] = s.y;
        T[row][c4 + 2] = s.z; T[row][c4 + 3] = s.w;
    }
    __syncthreads();

    // phase 2: out[i0+row][j0+c4..+3] = sum_p (Gp1+Gp2)[i0+row][j0+c4..] + T[c4+k][row]
    {
        float acc[4] = {0.f, 0.f, 0.f, 0.f};
        const long ro = (long)(i0 + row) * DIN + j0 + c4;
#pragma unroll
        for (int p = 0; p < 4; p++) {
            float4 v1 = *(const float4*)&Gp1[p * PS + b * GSL + ro];
            float4 v2 = *(const float4*)&Gp2[p * PS + b * GSL + ro];
            acc[0] += v1.x + v2.x; acc[1] += v1.y + v2.y;
            acc[2] += v1.z + v2.z; acc[3] += v1.w + v2.w;
        }
#pragma unroll
        for (int k = 0; k < 4; k++) acc[k] += T[c4 + k][row];
        uint2 hp, lp; split4pack(acc, hp, lp);
        *(uint2*)&Gh[b * GSL + ro] = hp;
        *(uint2*)&Gl[b * GSL + ro] = lp;
    }
}

// Vectorized fused reduce+transpose+split: FT[b][o][d] = split(sum_p Fp[p][b][d][o])
// grid (16,16,BB), 256 threads.
__global__ __launch_bounds__(256) void reduceF_splitFT_kernel(
    const float* __restrict__ Fp,
    __nv_bfloat16* __restrict__ FTh, __nv_bfloat16* __restrict__ FTl)
{
    __shared__ float T[32][33];
    const int tid = threadIdx.x;
    const int row = tid >> 3;
    const int c4 = (tid & 7) * 4;
    const int b = blockIdx.z, o0 = blockIdx.x * 32, d0 = blockIdx.y * 32;
    const long FS = (long)DIN * DOUT;
    const long PS = (long)BB * FS;

    // T[d_local][o_local] = sum_p Fp[d0+d][o0+o]
    {
        float4 s = make_float4(0.f, 0.f, 0.f, 0.f);
#pragma unroll
        for (int p = 0; p < 4; p++) {
            float4 v = *(const float4*)&Fp[p * PS + b * FS + (long)(d0 + row) * DOUT + o0 + c4];
            s.x += v.x; s.y += v.y; s.z += v.z; s.w += v.w;
        }
        T[row][c4 + 0] = s.x; T[row][c4 + 1] = s.y;
        T[row][c4 + 2] = s.z; T[row][c4 + 3] = s.w;
    }
    __syncthreads();

    // FT[o0+row][d0+c4..+3] = T[c4+k][row]
    {
        float acc[4];
#pragma unroll
        for (int k = 0; k < 4; k++) acc[k] = T[c4 + k][row];
        uint2 hp, lp; split4pack(acc, hp, lp);
        const long o = (long)b * DOUT * DIN + (long)(o0 + row) * DIN + d0 + c4;
        *(uint2*)&FTh[o] = hp;
        *(uint2*)&FTl[o] = lp;
    }
}

// ---------------------------------------------------------------------------
// bf16 tensor GEMM: C[128x128 fp32] = sum_k A[m,k]*B[n,k]
// PR=3: AhBh + AhBl + AlBh.  PR=1: AhBh only.
// KTv: k-chunk. GRAM=1: grid.z doubled; top half uses B=Bl_in, C=C2.
// ---------------------------------------------------------------------------
template <int PR, int KTv, int GRAM>
__global__ __launch_bounds__(256, 2) void tgemm_bf16(
    const __nv_bfloat16* __restrict__ Ah, const __nv_bfloat16* __restrict__ Al,
    const __nv_bfloat16* __restrict__ Bh, const __nv_bfloat16* __restrict__ Bl,
    float* __restrict__ C, float* __restrict__ C2,
    int K, int lda, int ldb, int ldc,
    long sAb, long sBb, long sCb, int nsplit, long splitStride)
{
    constexpr int STRIDEv = KTv + 8;
    constexpr int TILE = 128 * STRIDEv * 2;
    constexpr int NTILE = (PR == 1) ? 2 : 4;
    constexpr int BUF_Bv = NTILE * TILE;
    constexpr int S_AH = 0;
    constexpr int S_AL = (PR == 1) ? 0 : TILE;
    constexpr int S_BH = (PR == 1) ? TILE : 2 * TILE;
    constexpr int S_BL = (PR == 1) ? TILE : 3 * TILE;
    constexpr int SEGS = KTv / 8;

    extern __shared__ char sm[];
    const uint32_t sb = smem_u32(sm);

    const int tid = threadIdx.x;
    const int w = tid >> 5;
    const int lane = tid & 31;
    const int gid = lane >> 2;
    const int q = lane & 3;
    const int wr = w & 3;
    const int wc = w >> 2;

    int z = blockIdx.z;
    if (GRAM) {
        const int per = gridDim.z >> 1;
        if (z >= per) { z -= per; Bh = Bl; C = C2; }
    }
    const int split = z % nsplit;
    const int b = z / nsplit;
    Ah += (long)b * sAb; Al += (long)b * sAb;
    Bh += (long)b * sBb; Bl += (long)b * sBb;
    C += (long)b * sCb + (long)split * splitStride;

    const int m0 = blockIdx.y * 128;
    const int n0 = blockIdx.x * 128;
    const int Kc = K / nsplit;
    const int k0 = split * Kc;
    const int nchunks = Kc / KTv;

    float c[2][8][4];
#pragma unroll
    for (int mt = 0; mt < 2; mt++)
#pragma unroll
        for (int nt = 0; nt < 8; nt++)
#pragma unroll
            for (int i = 0; i < 4; i++) c[mt][nt][i] = 0.f;

    auto issue = [&](int ch, int buf) {
        const int kc = k0 + ch * KTv;
        const uint32_t base = sb + buf * BUF_Bv;
#pragma unroll
        for (int t = 0; t < 4; t++) {
            if (PR == 1 && (t & 1)) continue;
            const __nv_bfloat16* gp = (t == 0) ? Ah : (t == 1) ? Al : (t == 2) ? Bh : Bl;
            const int off = (t == 0) ? S_AH : (t == 1) ? S_AL : (t == 2) ? S_BH : S_BL;
            const int ld = (t < 2) ? lda : ldb;
            const int rb = (t < 2) ? m0 : n0;
#pragma unroll
            for (int p = 0; p < KTv / 16; p++) {
                const int f = p * 256 + tid;
                const int row = f / SEGS;
                const int seg = f % SEGS;
                cp_async16(base + off + (row * STRIDEv + seg * 8) * 2,
                           gp + (long)(rb + row) * ld + kc + seg * 8);
            }
        }
        asm volatile("cp.async.commit_group;" ::: "memory");
    };

    issue(0, 0);

    const int lrow = (lane & 7) + ((lane >> 3) & 1) * 8;
    const int lcol = (lane >> 4) * 8;

    for (int ch = 0; ch < nchunks; ch++) {
        const int cur = ch & 1;
        if (ch + 1 < nchunks) {
            issue(ch + 1, cur ^ 1);
            asm volatile("cp.async.wait_group 1;" ::: "memory");
        } else {
            asm volatile("cp.async.wait_group 0;" ::: "memory");
        }
        __syncthreads();

        const uint32_t base = sb + cur * BUF_Bv;
#pragma unroll
        for (int ks = 0; ks < KTv / 16; ks++) {
            const int kb = ks * 16;
#pragma unroll
            for (int pr = 0; pr < PR; pr++) {
                const uint32_t pa = base + ((pr == 2) ? S_AL : S_AH);
                const uint32_t pb = base + ((pr == 1) ? S_BL : S_BH);

                uint32_t a[2][4];
#pragma unroll
                for (int mt = 0; mt < 2; mt++) {
                    const int row = wr * 32 + mt * 16 + lrow;
                    ldm4(a[mt], pa + (row * STRIDEv + kb + lcol) * 2);
                }
#pragma unroll
                for (int ng = 0; ng < 4; ng++) {
                    const int row = wc * 64 + ng * 16 + lrow;
                    uint32_t bm[4];
                    ldm4(bm, pb + (row * STRIDEv + kb + lcol) * 2);
                    mma16816(c[0][ng * 2],     a[0], bm[0], bm[2]);
                    mma16816(c[0][ng * 2 + 1], a[0], bm[1], bm[3]);
                    mma16816(c[1][ng * 2],     a[1], bm[0], bm[2]);
                    mma16816(c[1][ng * 2 + 1], a[1], bm[1], bm[3]);
                }
            }
        }
        __syncthreads();
    }

#pragma unroll
    for (int mt = 0; mt < 2; mt++) {
        const int r = m0 + wr * 32 + mt * 16 + gid;
#pragma unroll
        for (int nt = 0; nt < 8; nt++) {
            const int col = n0 + wc * 64 + nt * 8 + q * 2;
            *(float2*)(C + (long)r * ldc + col)       = make_float2(c[mt][nt][0], c[mt][nt][1]);
            *(float2*)(C + (long)(r + 8) * ldc + col) = make_float2(c[mt][nt][2], c[mt][nt][3]);
        }
    }
}

// ---------------------------------------------------------------------------
// Small fp32 GEMM: 64x64 tile (middle chain steps 3-5)
// ---------------------------------------------------------------------------
template <int TRANSA>
__global__ __launch_bounds__(256) void gemm64(
    const float* __restrict__ A, const float* __restrict__ B, float* __restrict__ C,
    int M, int N, int K,
    int lda, int ldb, int ldc,
    long sAb, long sAh, long sBb, long sBh, long sCb, long sCh,
    int nh, int nsplit, long splitStride)
{
    int z = blockIdx.z;
    int split = z % nsplit; z /= nsplit;
    int h = z % nh;
    int b = z / nh;
    A += (long)b * sAb + (long)h * sAh;
    B += (long)b * sBb + (long)h * sBh;
    C += (long)b * sCb + (long)h * sCh + (long)split * splitStride;

    const int Kc = K / nsplit;
    const int k0 = split * Kc;

    __shared__ float As[16][64];
    __shared__ float Bs[16][64];

    const int m0 = blockIdx.y * 64;
    const int n0 = blockIdx.x * 64;
    const int tid = threadIdx.x;
    const int tx = tid & 15;
    const int ty = tid >> 4;

    float acc[4][4];
#pragma unroll
    for (int i = 0; i < 4; i++)
#pragma unroll
        for (int j = 0; j < 4; j++) acc[i][j] = 0.f;

    for (int kt = 0; kt < Kc; kt += 16) {
        if (TRANSA) {
            int k  = tid >> 4;
            int m4 = (tid & 15) * 4;
            float4 v = *reinterpret_cast<const float4*>(
                &A[(long)(k0 + kt + k) * lda + m0 + m4]);
            *reinterpret_cast<float4*>(&As[k][m4]) = v;
        } else {
            int m  = tid >> 2;
            int k4 = (tid & 3) * 4;
            float4 v = *reinterpret_cast<const float4*>(
                &A[(long)(m0 + m) * lda + (k0 + kt + k4)]);
            As[k4 + 0][m] = v.x;
            As[k4 + 1][m] = v.y;
            As[k4 + 2][m] = v.z;
            As[k4 + 3][m] = v.w;
        }
        {
            int k  = tid >> 4;
            int n4 = (tid & 15) * 4;
            float4 v = *reinterpret_cast<const float4*>(
                &B[(long)(k0 + kt + k) * ldb + n0 + n4]);
            *reinterpret_cast<float4*>(&Bs[k][n4]) = v;
        }
        __syncthreads();

#pragma unroll
        for (int k = 0; k < 16; k++) {
            float4 a = *reinterpret_cast<const float4*>(&As[k][ty * 4]);
            float4 bb = *reinterpret_cast<const float4*>(&Bs[k][tx * 4]);
            float av[4] = {a.x, a.y, a.z, a.w};
            float bv[4] = {bb.x, bb.y, bb.z, bb.w};
#pragma unroll
            for (int i = 0; i < 4; i++)
#pragma unroll
                for (int j = 0; j < 4; j++)
                    acc[i][j] += av[i] * bv[j];
        }
        __syncthreads();
    }

#pragma unroll
    for (int i = 0; i < 4; i++) {
        int m = m0 + ty * 4 + i;
        float4 v = make_float4(acc[i][0], acc[i][1], acc[i][2], acc[i][3]);
        *reinterpret_cast<float4*>(&C[(long)m * ldc + n0 + tx * 4]) = v;
    }
}

// float4-vectorized deterministic split-K reduce (n4 = n/4)
template <int P>
__global__ void reduceP4(float* __restrict__ dst, const float* __restrict__ src, int n4)
{
    int i = blockIdx.x * 256 + threadIdx.x;
    if (i < n4) {
        const float4* s4 = (const float4*)src;
        float4 acc = s4[i];
#pragma unroll
        for (int p = 1; p < P; p++) {
            float4 v = s4[(long)p * n4 + i];
            acc.x += v.x; acc.y += v.y; acc.z += v.z; acc.w += v.w;
        }
        ((float4*)dst)[i] = acc;
    }
}

// ---------------------------------------------------------------------------
extern "C" void kernel_launch(void* const* d_in, const int* in_sizes, int n_in,
                              void* d_out, int out_size)
{
    const float* x  = (const float*)d_in[0];
    const float* Wq = (const float*)d_in[1];
    const float* Wk = (const float*)d_in[2];
    const float* Wv = (const float*)d_in[3];
    const float* Wo = (const float*)d_in[4];
    float* out = (float*)d_out;

    float *Gp1, *Gp2, *P, *Mp, *M2, *T2;
    cudaGetSymbolAddress((void**)&Gp1, g_Gp1);
    cudaGetSymbolAddress((void**)&Gp2, g_Gp2);
    cudaGetSymbolAddress((void**)&P,   g_P);
    cudaGetSymbolAddress((void**)&Mp,  g_Mpart);
    cudaGetSymbolAddress((void**)&M2,  g_M2);
    cudaGetSymbolAddress((void**)&T2,  g_T2);

    __nv_bfloat16 *xh, *xl, *xTh, *xTl, *FTh, *FTl, *Gh, *Gl, *WkTh, *WkTl;
    cudaGetSymbolAddress((void**)&xh,   g_xh);
    cudaGetSymbolAddress((void**)&xl,   g_xl);
    cudaGetSymbolAddress((void**)&xTh,  g_xTh);
    cudaGetSymbolAddress((void**)&xTl,  g_xTl);
    cudaGetSymbolAddress((void**)&FTh,  g_FTh);
    cudaGetSymbolAddress((void**)&FTl,  g_FTl);
    cudaGetSymbolAddress((void**)&Gh,   g_Gh);
    cudaGetSymbolAddress((void**)&Gl,   g_Gl);
    cudaGetSymbolAddress((void**)&WkTh, g_WkTh);
    cudaGetSymbolAddress((void**)&WkTl, g_WkTl);

    const int TG1_SMEM = 2 * 2 * (128 * 72 * 2);   // KT=64, PR=1: 73728
    const int TG3_SMEM = 2 * 4 * (128 * 40 * 2);   // KT=32, PR=3: 81920
    cudaFuncSetAttribute((const void*)tgemm_bf16<1, 64, 1>,
                         cudaFuncAttributeMaxDynamicSharedMemorySize, TG1_SMEM);
    cudaFuncSetAttribute((const void*)tgemm_bf16<3, 32, 0>,
                         cudaFuncAttributeMaxDynamicSharedMemorySize, TG3_SMEM);

    const long LD   = (long)LL * DIN;
    const long GS   = (long)DIN * DIN;
    const long WKS  = (long)DIN * DK;
    const long PSH  = (long)DK * DIN;
    const long PSB  = (long)HH * PSH;
    const long MSH  = (long)DK * DV;
    const long MSB  = (long)HH * MSH;
    const long XTS  = (long)DIN * LL;

    // 0) split x; prep WkT
    split_x_kernel<<<dim3(DIN / 32, LL / 32, BB), dim3(32, 8)>>>(x, xh, xl, xTh, xTl);
    prep_WkT_kernel<<<dim3(DK / 32, DIN / 32, HH), dim3(32, 8)>>>(Wk, WkTh, WkTl);

    // 1) Gram, both symmetric products, ONE launch, split-K=4 -> 256 CTAs (1 wave)
    tgemm_bf16<1, 64, 1><<<dim3(4, 4, BB * 4 * 2), 256, TG1_SMEM>>>(
        xTh, xTh, xTh, xTl, Gp1, Gp2,
        LL, LL, LL, DIN, XTS, XTS, GS, 4, (long)BB * GS);
    reduceG_kernel<<<dim3(16, 16, BB), 256>>>(Gp1, Gp2, Gh, Gl);

    // 2) P_all[b] = WkT_flat @ G[b]  (split-K=4 -> grid 128; partials reuse Gp1)
    tgemm_bf16<3, 32, 0><<<dim3(4, 4, BB * 4), 256, TG3_SMEM>>>(
        WkTh, WkTl, Gh, Gl, Gp1, Gp1,
        DIN, DIN, DIN, DIN, 0, GS, GS, 4, (long)BB * GS);
    reduceP4<4><<<(int)((BB * GS / 4 + 255) / 256), 256>>>(P, Gp1, (int)(BB * GS / 4));

    // 3) M[b,h] = P[b,h] @ Wv[h]  (64x64, K=512), split-K=8 -> 128 CTAs
    gemm64<0><<<dim3(1, 1, BB * HH * 8), 256>>>(
        P, Wv, Mp, DK, DV, DIN,
        DIN, DV, DV,
        PSB, PSH, 0, WKS, MSB, MSH,
        HH, 8, (long)BB * HH * DK * DV);
    reduceP4<8><<<(BB * HH * DK * DV / 4 + 255) / 256, 256>>>(M2, Mp, BB * HH * DK * DV / 4);

    // 4) T2cat[b][:, h*64:] = Wq[h] @ M[b,h]  (512x64, K=64), 128 CTAs
    gemm64<0><<<dim3(1, 8, BB * HH), 256>>>(
        Wq, M2, T2, DIN, DV, DK,
        DK, DV, HH * DV,
        0, WKS, MSB, MSH, (long)DIN * HH * DV, (long)DV,
        HH, 1, 0);

    // 5) F partials = T2cat[b] @ Wo_flat  (split-K=4 -> 256 CTAs; partials in Gp2)
    gemm64<0><<<dim3(8, 8, BB * 4), 256>>>(
        T2, Wo, Gp2, DIN, DOUT, HH * DV,
        HH * DV, DOUT, DOUT,
        (long)DIN * HH * DV, 0, 0, 0, (long)DIN * DOUT, 0,
        1, 4, (long)BB * DIN * DOUT);

    // 5b) fused: F = sum partials; FT bf16 hi/lo (transposed) in one pass
    reduceF_splitFT_kernel<<<dim3(16, 16, BB), 256>>>(Gp2, FTh, FTl);

    // 6) out[b] = x[b] @ F[b]  (tensor, 3-product), 256 CTAs
    tgemm_bf16<3, 32, 0><<<dim3(4, 32, BB), 256, TG3_SMEM>>>(
        xh, xl, FTh, FTl, out, out,
        DIN, DIN, DIN, DOUT,
        LD, (long)DOUT * DIN, (long)LL * DOUT, 1, 0);
}

// round 15
// speedup vs baseline: 1.1124x; 1.0557x over previous
#include <cuda_runtime.h>
#include <cuda_bf16.h>
#include <cstdint>

#define BB 2
#define LL 4096
#define DIN 512
#define HH 8
#define DK 64
#define DV 64
#define DOUT 512

// ---------------------------------------------------------------------------
// Scratch (__device__ globals; no allocations allowed)
// ---------------------------------------------------------------------------
__device__ float g_Gp1[4 * BB * DIN * DIN];       // Gram partials XhXh / step2 P partials
__device__ float g_Gp2[4 * BB * DIN * DIN];       // Gram partials XhXl / step5 F partials
__device__ float g_Mpart[8 * BB * HH * DK * DV];  // step-3 split-K partials
__device__ float g_T2[BB * DIN * (HH * DV)];      // T2cat[b] (512 x 512)

// bf16 hi/lo split arrays
__device__ __nv_bfloat16 g_xh [BB * LL * DIN];    // x direct  [b][l][d]
__device__ __nv_bfloat16 g_xl [BB * LL * DIN];
__device__ __nv_bfloat16 g_xTh[BB * DIN * LL];    // x^T       [b][d][l]
__device__ __nv_bfloat16 g_xTl[BB * DIN * LL];
__device__ __nv_bfloat16 g_FTh[BB * DOUT * DIN];  // F^T       [b][o][d]
__device__ __nv_bfloat16 g_FTl[BB * DOUT * DIN];
__device__ __nv_bfloat16 g_Gh [BB * DIN * DIN];   // G bf16 hi (symmetric)
__device__ __nv_bfloat16 g_Gl [BB * DIN * DIN];   // G bf16 lo
__device__ __nv_bfloat16 g_WkTh[HH * DK * DIN];   // WkT flat: row h*64+k, col d
__device__ __nv_bfloat16 g_WkTl[HH * DK * DIN];

// ---------------------------------------------------------------------------
// Helpers
// ---------------------------------------------------------------------------
__device__ __forceinline__ uint32_t smem_u32(const void* p) {
    uint32_t a;
    asm("{ .reg .u64 t; cvta.to.shared.u64 t, %1; cvt.u32.u64 %0, t; }" : "=r"(a) : "l"(p));
    return a;
}
__device__ __forceinline__ void cp_async16(uint32_t saddr, const void* gptr) {
    asm volatile("cp.async.ca.shared.global [%0], [%1], 16;" :: "r"(saddr), "l"(gptr));
}
__device__ __forceinline__ void ldm4(uint32_t* r, uint32_t addr) {
    asm volatile("ldmatrix.sync.aligned.m8n8.x4.shared.b16 {%0,%1,%2,%3}, [%4];"
        : "=r"(r[0]), "=r"(r[1]), "=r"(r[2]), "=r"(r[3]) : "r"(addr));
}
__device__ __forceinline__ void mma16816(float* c, const uint32_t* a,
                                         uint32_t b0, uint32_t b1) {
    asm volatile(
        "mma.sync.aligned.m16n8k16.row.col.f32.bf16.bf16.f32 "
        "{%0,%1,%2,%3}, {%4,%5,%6,%7}, {%8,%9}, {%0,%1,%2,%3};"
        : "+f"(c[0]), "+f"(c[1]), "+f"(c[2]), "+f"(c[3])
        : "r"(a[0]), "r"(a[1]), "r"(a[2]), "r"(a[3]), "r"(b0), "r"(b1));
}
__device__ __forceinline__ void bf16split(float v, __nv_bfloat16& h, __nv_bfloat16& l) {
    h = __float2bfloat16(v);
    l = __float2bfloat16(v - __bfloat162float(h));
}
// split 4 floats -> packed hi (uint2) + lo (uint2)
__device__ __forceinline__ void split4pack(const float* v, uint2& hp, uint2& lp) {
    __nv_bfloat16 h[4], l[4];
#pragma unroll
    for (int i = 0; i < 4; i++) bf16split(v[i], h[i], l[i]);
    hp.x = (uint32_t)__bfloat16_as_ushort(h[0]) | ((uint32_t)__bfloat16_as_ushort(h[1]) << 16);
    hp.y = (uint32_t)__bfloat16_as_ushort(h[2]) | ((uint32_t)__bfloat16_as_ushort(h[3]) << 16);
    lp.x = (uint32_t)__bfloat16_as_ushort(l[0]) | ((uint32_t)__bfloat16_as_ushort(l[1]) << 16);
    lp.y = (uint32_t)__bfloat16_as_ushort(l[2]) | ((uint32_t)__bfloat16_as_ushort(l[3]) << 16);
}

// ---------------------------------------------------------------------------
// Split / prep kernels
// ---------------------------------------------------------------------------
// Vectorized: one 32x32 tile per CTA; float4 loads, packed uint2 stores.
__global__ __launch_bounds__(256) void split_x_kernel(
    const float* __restrict__ x,
    __nv_bfloat16* __restrict__ xh, __nv_bfloat16* __restrict__ xl,
    __nv_bfloat16* __restrict__ xTh, __nv_bfloat16* __restrict__ xTl)
{
    __shared__ float T[32][33];
    const int tid = threadIdx.x;
    const int row = tid >> 3;          // 0..31 (l-local)
    const int c4 = (tid & 7) * 4;      // 0..28 (d-local)
    const int b = blockIdx.z, d0 = blockIdx.x * 32, l0 = blockIdx.y * 32;

    // phase 1: direct layout
    {
        float4 v = *(const float4*)&x[(long)b * LL * DIN + (long)(l0 + row) * DIN + d0 + c4];
        float vv[4] = {v.x, v.y, v.z, v.w};
        uint2 hp, lp; split4pack(vv, hp, lp);
        const long o = (long)b * LL * DIN + (long)(l0 + row) * DIN + d0 + c4;
        *(uint2*)&xh[o] = hp;
        *(uint2*)&xl[o] = lp;
        T[row][c4 + 0] = v.x; T[row][c4 + 1] = v.y;
        T[row][c4 + 2] = v.z; T[row][c4 + 3] = v.w;
    }
    __syncthreads();
    // phase 2: transposed layout — xT[d0+row][l0+c4+k] = T[c4+k][row]
    {
        float a[4];
#pragma unroll
        for (int k = 0; k < 4; k++) a[k] = T[c4 + k][row];
        uint2 hp, lp; split4pack(a, hp, lp);
        const long o = (long)b * DIN * LL + (long)(d0 + row) * LL + l0 + c4;
        *(uint2*)&xTh[o] = hp;
        *(uint2*)&xTl[o] = lp;
    }
}

// WkT[h*64+k][d] = Wk[h][d][k], bf16 hi/lo
__global__ __launch_bounds__(256) void prep_WkT_kernel(
    const float* __restrict__ Wk,
    __nv_bfloat16* __restrict__ WkTh, __nv_bfloat16* __restrict__ WkTl)
{
    __shared__ float tile[32][33];
    const int tx = threadIdx.x, ty = threadIdx.y;
    const int h = blockIdx.z, k0 = blockIdx.x * 32, d0 = blockIdx.y * 32;
    const float* W = Wk + (long)h * DIN * DK;

#pragma unroll
    for (int r = ty; r < 32; r += 8)
        tile[r][tx] = W[(long)(d0 + r) * DK + k0 + tx];
    __syncthreads();
#pragma unroll
    for (int ii = ty; ii < 32; ii += 8) {
        float v = tile[tx][ii];
        __nv_bfloat16 hh, lo; bf16split(v, hh, lo);
        long o = (long)(h * DK + k0 + ii) * DIN + d0 + tx;
        WkTh[o] = hh; WkTl[o] = lo;
    }
}

// Vectorized reduceG: G = sum_p Gp1 + sum_p Gp2 + (sum_p Gp2)^T ; bf16 hi/lo.
__global__ __launch_bounds__(256) void reduceG_kernel(
    const float* __restrict__ Gp1, const float* __restrict__ Gp2,
    __nv_bfloat16* __restrict__ Gh, __nv_bfloat16* __restrict__ Gl)
{
    __shared__ float T[32][33];
    const int tid = threadIdx.x;
    const int row = tid >> 3;
    const int c4 = (tid & 7) * 4;
    const int b = blockIdx.z, j0 = blockIdx.x * 32, i0 = blockIdx.y * 32;
    const long GSL = (long)DIN * DIN;
    const long PS = (long)BB * GSL;

    {
        float4 s = make_float4(0.f, 0.f, 0.f, 0.f);
#pragma unroll
        for (int p = 0; p < 4; p++) {
            float4 v = *(const float4*)&Gp2[p * PS + b * GSL + (long)(j0 + row) * DIN + i0 + c4];
            s.x += v.x; s.y += v.y; s.z += v.z; s.w += v.w;
        }
        T[row][c4 + 0] = s.x; T[row][c4 + 1] = s.y;
        T[row][c4 + 2] = s.z; T[row][c4 + 3] = s.w;
    }
    __syncthreads();
    {
        float acc[4] = {0.f, 0.f, 0.f, 0.f};
        const long ro = (long)(i0 + row) * DIN + j0 + c4;
#pragma unroll
        for (int p = 0; p < 4; p++) {
            float4 v1 = *(const float4*)&Gp1[p * PS + b * GSL + ro];
            float4 v2 = *(const float4*)&Gp2[p * PS + b * GSL + ro];
            acc[0] += v1.x + v2.x; acc[1] += v1.y + v2.y;
            acc[2] += v1.z + v2.z; acc[3] += v1.w + v2.w;
        }
#pragma unroll
        for (int k = 0; k < 4; k++) acc[k] += T[c4 + k][row];
        uint2 hp, lp; split4pack(acc, hp, lp);
        *(uint2*)&Gh[b * GSL + ro] = hp;
        *(uint2*)&Gl[b * GSL + ro] = lp;
    }
}

// Vectorized fused reduce+transpose+split: FT[b][o][d] = split(sum_p Fp[p][b][d][o])
__global__ __launch_bounds__(256) void reduceF_splitFT_kernel(
    const float* __restrict__ Fp,
    __nv_bfloat16* __restrict__ FTh, __nv_bfloat16* __restrict__ FTl)
{
    __shared__ float T[32][33];
    const int tid = threadIdx.x;
    const int row = tid >> 3;
    const int c4 = (tid & 7) * 4;
    const int b = blockIdx.z, o0 = blockIdx.x * 32, d0 = blockIdx.y * 32;
    const long FS = (long)DIN * DOUT;
    const long PS = (long)BB * FS;

    {
        float4 s = make_float4(0.f, 0.f, 0.f, 0.f);
#pragma unroll
        for (int p = 0; p < 4; p++) {
            float4 v = *(const float4*)&Fp[p * PS + b * FS + (long)(d0 + row) * DOUT + o0 + c4];
            s.x += v.x; s.y += v.y; s.z += v.z; s.w += v.w;
        }
        T[row][c4 + 0] = s.x; T[row][c4 + 1] = s.y;
        T[row][c4 + 2] = s.z; T[row][c4 + 3] = s.w;
    }
    __syncthreads();
    {
        float acc[4];
#pragma unroll
        for (int k = 0; k < 4; k++) acc[k] = T[c4 + k][row];
        uint2 hp, lp; split4pack(acc, hp, lp);
        const long o = (long)b * DOUT * DIN + (long)(o0 + row) * DIN + d0 + c4;
        *(uint2*)&FTh[o] = hp;
        *(uint2*)&FTl[o] = lp;
    }
}

// ---------------------------------------------------------------------------
// bf16 tensor GEMM: C[128x128 fp32] = sum_k A[m,k]*B[n,k]
// PR=3: AhBh + AhBl + AlBh.  PR=1: AhBh only.
// KTv: k-chunk. GRAM=1: grid.z doubled; top half uses B=Bl_in, C=C2.
// ---------------------------------------------------------------------------
template <int PR, int KTv, int GRAM>
__global__ __launch_bounds__(256, 2) void tgemm_bf16(
    const __nv_bfloat16* __restrict__ Ah, const __nv_bfloat16* __restrict__ Al,
    const __nv_bfloat16* __restrict__ Bh, const __nv_bfloat16* __restrict__ Bl,
    float* __restrict__ C, float* __restrict__ C2,
    int K, int lda, int ldb, int ldc,
    long sAb, long sBb, long sCb, int nsplit, long splitStride)
{
    constexpr int STRIDEv = KTv + 8;
    constexpr int TILE = 128 * STRIDEv * 2;
    constexpr int NTILE = (PR == 1) ? 2 : 4;
    constexpr int BUF_Bv = NTILE * TILE;
    constexpr int S_AH = 0;
    constexpr int S_AL = (PR == 1) ? 0 : TILE;
    constexpr int S_BH = (PR == 1) ? TILE : 2 * TILE;
    constexpr int S_BL = (PR == 1) ? TILE : 3 * TILE;
    constexpr int SEGS = KTv / 8;

    extern __shared__ char sm[];
    const uint32_t sb = smem_u32(sm);

    const int tid = threadIdx.x;
    const int w = tid >> 5;
    const int lane = tid & 31;
    const int gid = lane >> 2;
    const int q = lane & 3;
    const int wr = w & 3;
    const int wc = w >> 2;

    int z = blockIdx.z;
    if (GRAM) {
        const int per = gridDim.z >> 1;
        if (z >= per) { z -= per; Bh = Bl; C = C2; }
    }
    const int split = z % nsplit;
    const int b = z / nsplit;
    Ah += (long)b * sAb; Al += (long)b * sAb;
    Bh += (long)b * sBb; Bl += (long)b * sBb;
    C += (long)b * sCb + (long)split * splitStride;

    const int m0 = blockIdx.y * 128;
    const int n0 = blockIdx.x * 128;
    const int Kc = K / nsplit;
    const int k0 = split * Kc;
    const int nchunks = Kc / KTv;

    float c[2][8][4];
#pragma unroll
    for (int mt = 0; mt < 2; mt++)
#pragma unroll
        for (int nt = 0; nt < 8; nt++)
#pragma unroll
            for (int i = 0; i < 4; i++) c[mt][nt][i] = 0.f;

    auto issue = [&](int ch, int buf) {
        const int kc = k0 + ch * KTv;
        const uint32_t base = sb + buf * BUF_Bv;
#pragma unroll
        for (int t = 0; t < 4; t++) {
            if (PR == 1 && (t & 1)) continue;
            const __nv_bfloat16* gp = (t == 0) ? Ah : (t == 1) ? Al : (t == 2) ? Bh : Bl;
            const int off = (t == 0) ? S_AH : (t == 1) ? S_AL : (t == 2) ? S_BH : S_BL;
            const int ld = (t < 2) ? lda : ldb;
            const int rb = (t < 2) ? m0 : n0;
#pragma unroll
            for (int p = 0; p < KTv / 16; p++) {
                const int f = p * 256 + tid;
                const int row = f / SEGS;
                const int seg = f % SEGS;
                cp_async16(base + off + (row * STRIDEv + seg * 8) * 2,
                           gp + (long)(rb + row) * ld + kc + seg * 8);
            }
        }
        asm volatile("cp.async.commit_group;" ::: "memory");
    };

    issue(0, 0);

    const int lrow = (lane & 7) + ((lane >> 3) & 1) * 8;
    const int lcol = (lane >> 4) * 8;

    for (int ch = 0; ch < nchunks; ch++) {
        const int cur = ch & 1;
        if (ch + 1 < nchunks) {
            issue(ch + 1, cur ^ 1);
            asm volatile("cp.async.wait_group 1;" ::: "memory");
        } else {
            asm volatile("cp.async.wait_group 0;" ::: "memory");
        }
        __syncthreads();

        const uint32_t base = sb + cur * BUF_Bv;
#pragma unroll
        for (int ks = 0; ks < KTv / 16; ks++) {
            const int kb = ks * 16;
#pragma unroll
            for (int pr = 0; pr < PR; pr++) {
                const uint32_t pa = base + ((pr == 2) ? S_AL : S_AH);
                const uint32_t pb = base + ((pr == 1) ? S_BL : S_BH);

                uint32_t a[2][4];
#pragma unroll
                for (int mt = 0; mt < 2; mt++) {
                    const int row = wr * 32 + mt * 16 + lrow;
                    ldm4(a[mt], pa + (row * STRIDEv + kb + lcol) * 2);
                }
#pragma unroll
                for (int ng = 0; ng < 4; ng++) {
                    const int row = wc * 64 + ng * 16 + lrow;
                    uint32_t bm[4];
                    ldm4(bm, pb + (row * STRIDEv + kb + lcol) * 2);
                    mma16816(c[0][ng * 2],     a[0], bm[0], bm[2]);
                    mma16816(c[0][ng * 2 + 1], a[0], bm[1], bm[3]);
                    mma16816(c[1][ng * 2],     a[1], bm[0], bm[2]);
                    mma16816(c[1][ng * 2 + 1], a[1], bm[1], bm[3]);
                }
            }
        }
        __syncthreads();
    }

#pragma unroll
    for (int mt = 0; mt < 2; mt++) {
        const int r = m0 + wr * 32 + mt * 16 + gid;
#pragma unroll
        for (int nt = 0; nt < 8; nt++) {
            const int col = n0 + wc * 64 + nt * 8 + q * 2;
            *(float2*)(C + (long)r * ldc + col)       = make_float2(c[mt][nt][0], c[mt][nt][1]);
            *(float2*)(C + (long)(r + 8) * ldc + col) = make_float2(c[mt][nt][2], c[mt][nt][3]);
        }
    }
}

// ---------------------------------------------------------------------------
// Small fp32 GEMM: 64x64 tile (middle chain steps 3-5).
// REDA/REDB: number of split-K partials summed inline during the A/B tile
// loads (fixed order -> deterministic).  psA/psB: partial strides.
// ---------------------------------------------------------------------------
template <int TRANSA, int REDA, int REDB>
__global__ __launch_bounds__(256) void gemm64(
    const float* __restrict__ A, const float* __restrict__ B, float* __restrict__ C,
    int M, int N, int K,
    int lda, int ldb, int ldc,
    long sAb, long sAh, long sBb, long sBh, long sCb, long sCh,
    int nh, int nsplit, long splitStride, long psA, long psB)
{
    int z = blockIdx.z;
    int split = z % nsplit; z /= nsplit;
    int h = z % nh;
    int b = z / nh;
    A += (long)b * sAb + (long)h * sAh;
    B += (long)b * sBb + (long)h * sBh;
    C += (long)b * sCb + (long)h * sCh + (long)split * splitStride;

    const int Kc = K / nsplit;
    const int k0 = split * Kc;

    __shared__ float As[16][64];
    __shared__ float Bs[16][64];

    const int m0 = blockIdx.y * 64;
    const int n0 = blockIdx.x * 64;
    const int tid = threadIdx.x;
    const int tx = tid & 15;
    const int ty = tid >> 4;

    float acc[4][4];
#pragma unroll
    for (int i = 0; i < 4; i++)
#pragma unroll
        for (int j = 0; j < 4; j++) acc[i][j] = 0.f;

    for (int kt = 0; kt < Kc; kt += 16) {
        if (TRANSA) {
            int k  = tid >> 4;
            int m4 = (tid & 15) * 4;
            const float* ap = &A[(long)(k0 + kt + k) * lda + m0 + m4];
            float4 v = *(const float4*)ap;
#pragma unroll
            for (int p = 1; p < REDA; p++) {
                float4 u = *(const float4*)(ap + (long)p * psA);
                v.x += u.x; v.y += u.y; v.z += u.z; v.w += u.w;
            }
            *reinterpret_cast<float4*>(&As[k][m4]) = v;
        } else {
            int m  = tid >> 2;
            int k4 = (tid & 3) * 4;
            const float* ap = &A[(long)(m0 + m) * lda + (k0 + kt + k4)];
            float4 v = *(const float4*)ap;
#pragma unroll
            for (int p = 1; p < REDA; p++) {
                float4 u = *(const float4*)(ap + (long)p * psA);
                v.x += u.x; v.y += u.y; v.z += u.z; v.w += u.w;
            }
            As[k4 + 0][m] = v.x;
            As[k4 + 1][m] = v.y;
            As[k4 + 2][m] = v.z;
            As[k4 + 3][m] = v.w;
        }
        {
            int k  = tid >> 4;
            int n4 = (tid & 15) * 4;
            const float* bp = &B[(long)(k0 + kt + k) * ldb + n0 + n4];
            float4 v = *(const float4*)bp;
#pragma unroll
            for (int p = 1; p < REDB; p++) {
                float4 u = *(const float4*)(bp + (long)p * psB);
                v.x += u.x; v.y += u.y; v.z += u.z; v.w += u.w;
            }
            *reinterpret_cast<float4*>(&Bs[k][n4]) = v;
        }
        __syncthreads();

#pragma unroll
        for (int k = 0; k < 16; k++) {
            float4 a = *reinterpret_cast<const float4*>(&As[k][ty * 4]);
            float4 bb = *reinterpret_cast<const float4*>(&Bs[k][tx * 4]);
            float av[4] = {a.x, a.y, a.z, a.w};
            float bv[4] = {bb.x, bb.y, bb.z, bb.w};
#pragma unroll
            for (int i = 0; i < 4; i++)
#pragma unroll
                for (int j = 0; j < 4; j++)
                    acc[i][j] += av[i] * bv[j];
        }
        __syncthreads();
    }

#pragma unroll
    for (int i = 0; i < 4; i++) {
        int m = m0 + ty * 4 + i;
        float4 v = make_float4(acc[i][0], acc[i][1], acc[i][2], acc[i][3]);
        *reinterpret_cast<float4*>(&C[(long)m * ldc + n0 + tx * 4]) = v;
    }
}

// ---------------------------------------------------------------------------
extern "C" void kernel_launch(void* const* d_in, const int* in_sizes, int n_in,
                              void* d_out, int out_size)
{
    const float* x  = (const float*)d_in[0];
    const float* Wq = (const float*)d_in[1];
    const float* Wk = (const float*)d_in[2];
    const float* Wv = (const float*)d_in[3];
    const float* Wo = (const float*)d_in[4];
    float* out = (float*)d_out;

    float *Gp1, *Gp2, *Mp, *T2;
    cudaGetSymbolAddress((void**)&Gp1, g_Gp1);
    cudaGetSymbolAddress((void**)&Gp2, g_Gp2);
    cudaGetSymbolAddress((void**)&Mp,  g_Mpart);
    cudaGetSymbolAddress((void**)&T2,  g_T2);

    __nv_bfloat16 *xh, *xl, *xTh, *xTl, *FTh, *FTl, *Gh, *Gl, *WkTh, *WkTl;
    cudaGetSymbolAddress((void**)&xh,   g_xh);
    cudaGetSymbolAddress((void**)&xl,   g_xl);
    cudaGetSymbolAddress((void**)&xTh,  g_xTh);
    cudaGetSymbolAddress((void**)&xTl,  g_xTl);
    cudaGetSymbolAddress((void**)&FTh,  g_FTh);
    cudaGetSymbolAddress((void**)&FTl,  g_FTl);
    cudaGetSymbolAddress((void**)&Gh,   g_Gh);
    cudaGetSymbolAddress((void**)&Gl,   g_Gl);
    cudaGetSymbolAddress((void**)&WkTh, g_WkTh);
    cudaGetSymbolAddress((void**)&WkTl, g_WkTl);

    const int TG1_SMEM = 2 * 2 * (128 * 72 * 2);   // KT=64, PR=1: 73728
    const int TG3_SMEM = 2 * 4 * (128 * 40 * 2);   // KT=32, PR=3: 81920
    cudaFuncSetAttribute((const void*)tgemm_bf16<1, 64, 1>,
                         cudaFuncAttributeMaxDynamicSharedMemorySize, TG1_SMEM);
    cudaFuncSetAttribute((const void*)tgemm_bf16<3, 32, 0>,
                         cudaFuncAttributeMaxDynamicSharedMemorySize, TG3_SMEM);

    const long LD   = (long)LL * DIN;
    const long GS   = (long)DIN * DIN;
    const long WKS  = (long)DIN * DK;
    const long PSH  = (long)DK * DIN;
    const long PSB  = (long)HH * PSH;      // = GS
    const long MSH  = (long)DK * DV;
    const long MSB  = (long)HH * MSH;
    const long XTS  = (long)DIN * LL;

    // 0) split x (vectorized); prep WkT
    split_x_kernel<<<dim3(DIN / 32, LL / 32, BB), 256>>>(x, xh, xl, xTh, xTl);
    prep_WkT_kernel<<<dim3(DK / 32, DIN / 32, HH), dim3(32, 8)>>>(Wk, WkTh, WkTl);

    // 1) Gram, both symmetric products, ONE launch, split-K=4 -> 256 CTAs
    tgemm_bf16<1, 64, 1><<<dim3(4, 4, BB * 4 * 2), 256, TG1_SMEM>>>(
        xTh, xTh, xTh, xTl, Gp1, Gp2,
        LL, LL, LL, DIN, XTS, XTS, GS, 4, (long)BB * GS);
    reduceG_kernel<<<dim3(16, 16, BB), 256>>>(Gp1, Gp2, Gh, Gl);

    // 2) P partials = WkT_flat @ G[b]  (split-K=4 -> grid 128; partials in Gp1,
    //    consumed directly by step 3 — no separate reduce)
    tgemm_bf16<3, 32, 0><<<dim3(4, 4, BB * 4), 256, TG3_SMEM>>>(
        WkTh, WkTl, Gh, Gl, Gp1, Gp1,
        DIN, DIN, DIN, DIN, 0, GS, GS, 4, (long)BB * GS);

    // 3) M partials[b,h] = (sum_p Ppart)[b,h] @ Wv[h]  (64x64, K=512),
    //    split-K=8 -> 128 CTAs; A-load sums the 4 step-2 partials inline.
    gemm64<0, 4, 1><<<dim3(1, 1, BB * HH * 8), 256>>>(
        Gp1, Wv, Mp, DK, DV, DIN,
        DIN, DV, DV,
        PSB, PSH, 0, WKS, MSB, MSH,
        HH, 8, (long)BB * HH * DK * DV,
        /*psA=*/(long)BB * GS, /*psB=*/0);

    // 4) T2cat[b][:, h*64:] = Wq[h] @ (sum_p Mpart)[b,h]  (512x64, K=64),
    //    128 CTAs; B-load sums the 8 step-3 partials inline.
    gemm64<0, 1, 8><<<dim3(1, 8, BB * HH), 256>>>(
        Wq, Mp, T2, DIN, DV, DK,
        DK, DV, HH * DV,
        0, WKS, MSB, MSH, (long)DIN * HH * DV, (long)DV,
        HH, 1, 0,
        /*psA=*/0, /*psB=*/(long)BB * HH * DK * DV);

    // 5) F partials = T2cat[b] @ Wo_flat  (split-K=4 -> 256 CTAs; partials in Gp2)
    gemm64<0, 1, 1><<<dim3(8, 8, BB * 4), 256>>>(
        T2, Wo, Gp2, DIN, DOUT, HH * DV,
        HH * DV, DOUT, DOUT,
        (long)DIN * HH * DV, 0, 0, 0, (long)DIN * DOUT, 0,
        1, 4, (long)BB * DIN * DOUT, 0, 0);

    // 5b) fused: F = sum partials; FT bf16 hi/lo (transposed) in one pass
    reduceF_splitFT_kernel<<<dim3(16, 16, BB), 256>>>(Gp2, FTh, FTl);

    // 6) out[b] = x[b] @ F[b]  (tensor, 3-product), 256 CTAs
    tgemm_bf16<3, 32, 0><<<dim3(4, 32, BB), 256, TG3_SMEM>>>(
        xh, xl, FTh, FTl, out, out,
        DIN, DIN, DIN, DOUT,
        LD, (long)DOUT * DIN, (long)LL * DOUT, 1, 0);
}